// round 11
// baseline (speedup 1.0000x reference)
#include <cuda_runtime.h>
#include <math.h>
#include <stdint.h>

#define D_MODEL 1024
#define D_FF    4096
#define NE      8
#define NT      8192
#define ROWS_MAX 17408
#define NTILES  136             // ROWS_MAX/128 m-tiles
#define G1_TILES (NTILES * 32)  // 4352
#define G2_TILES (NTILES * 8)   // 1088

// ---------------- static scratch (no runtime allocation allowed) ----------------
__device__ int   g_topk_idx[NT * 2];
__device__ float g_topk_prob[NT * 2];
__device__ int   g_pos[NT * 2];
__device__ int   g_counts[NE];
__device__ float g_probs_sum[NE];
__device__ int   g_poff[NE + 1];
__device__ int   g_cursor[NE];
__device__ int   g_cursor2;              // persistent-kernel tile queue
__device__ int   g_done[NTILES];         // per-m-block GEMM1 completion counters
__device__ float g_xa[(size_t)ROWS_MAX * D_MODEL];        // permuted + tf32-rounded x
__device__ float g_h[(size_t)ROWS_MAX * D_FF];            // GEMM1 out, tf32-rounded fp32
__device__ float g_y[(size_t)ROWS_MAX * D_MODEL];         // GEMM2 out fp32

// ---------------- PTX helpers (arch-portable only) ----------------
__device__ __forceinline__ uint32_t smem_to_u32(const void* p) {
    uint32_t a;
    asm("{ .reg .u64 t; cvta.to.shared.u64 t, %1; cvt.u32.u64 %0, t; }" : "=r"(a) : "l"(p));
    return a;
}
__device__ __forceinline__ void cp16(uint32_t s, const void* g) {
    asm volatile("cp.async.cg.shared.global [%0], [%1], 16;\n" :: "r"(s), "l"(g) : "memory");
}
#define CP_COMMIT() asm volatile("cp.async.commit_group;\n" ::: "memory")
#define CP_WAIT(n)  asm volatile("cp.async.wait_group %0;\n" :: "n"(n) : "memory")

__device__ __forceinline__ void mma_tf32(float* c, const unsigned* a, const unsigned* b) {
    asm volatile(
        "mma.sync.aligned.m16n8k8.row.col.f32.tf32.tf32.f32 "
        "{%0,%1,%2,%3}, {%4,%5,%6,%7}, {%8,%9}, {%0,%1,%2,%3};\n"
        : "+f"(c[0]), "+f"(c[1]), "+f"(c[2]), "+f"(c[3])
        : "r"(a[0]), "r"(a[1]), "r"(a[2]), "r"(a[3]), "r"(b[0]), "r"(b[1]));
}
__device__ __forceinline__ float rna_tf32(float v) {
    float r;
    asm("cvt.rna.tf32.f32 %0, %1;\n" : "=f"(r) : "f"(v));
    return r;
}
__device__ __forceinline__ unsigned rna_tf32_u(float v) {
    float r;
    asm("cvt.rna.tf32.f32 %0, %1;\n" : "=f"(r) : "f"(v));
    return __float_as_uint(r);
}
__device__ __forceinline__ float4 rna_tf32_4(float4 v) {
    v.x = rna_tf32(v.x); v.y = rna_tf32(v.y);
    v.z = rna_tf32(v.z); v.w = rna_tf32(v.w);
    return v;
}

// ---------------- init (per call: counters + queue state) ----------------
__global__ void k_init() {
    int i = threadIdx.x;
    if (i < NE) { g_counts[i] = 0; g_probs_sum[i] = 0.f; g_cursor[i] = 0; }
    if (i == 0) g_cursor2 = 0;
    if (i < NTILES) g_done[i] = 0;
}

// ---------------- router: 1 warp per token ----------------
__global__ void __launch_bounds__(256) k_router(const float* __restrict__ x,
                                                const float* __restrict__ gw,
                                                const float* __restrict__ gb) {
    __shared__ float gws[NE * D_MODEL];
    __shared__ float psum[NE];
    __shared__ int   scnt[NE];
    int tid = threadIdx.x;
    for (int i = tid; i < NE * D_MODEL; i += 256) {
        int d = i >> 3, e = i & 7;
        gws[e * D_MODEL + d] = gw[i];
    }
    if (tid < NE) { psum[tid] = 0.f; scnt[tid] = 0; }
    __syncthreads();

    int lane = tid & 31, warp = tid >> 5;
    int t = blockIdx.x * 8 + warp;
    const float* xr = x + (size_t)t * D_MODEL;

    float acc[NE];
#pragma unroll
    for (int e = 0; e < NE; e++) acc[e] = 0.f;
    for (int i = 0; i < D_MODEL / 32; i++) {
        int d = i * 32 + lane;
        float xv = xr[d];
#pragma unroll
        for (int e = 0; e < NE; e++) acc[e] += xv * gws[e * D_MODEL + d];
    }
#pragma unroll
    for (int e = 0; e < NE; e++)
        for (int off = 16; off > 0; off >>= 1)
            acc[e] += __shfl_xor_sync(0xffffffffu, acc[e], off);

    if (lane == 0) {
        float l[NE], p[NE];
        float m = -1e30f;
#pragma unroll
        for (int e = 0; e < NE; e++) { l[e] = acc[e] + gb[e]; m = fmaxf(m, l[e]); }
        float s = 0.f;
#pragma unroll
        for (int e = 0; e < NE; e++) { p[e] = expf(l[e] - m); s += p[e]; }
        float inv = 1.f / s;
#pragma unroll
        for (int e = 0; e < NE; e++) { p[e] *= inv; atomicAdd(&psum[e], p[e]); }
        int e1 = 0;
#pragma unroll
        for (int e = 1; e < NE; e++) if (p[e] > p[e1]) e1 = e;
        int e2 = -1;
#pragma unroll
        for (int e = 0; e < NE; e++) {
            if (e == e1) continue;
            if (e2 < 0 || p[e] > p[e2]) e2 = e;
        }
        float pr = 1.f / (p[e1] + p[e2]);
        g_topk_idx[2 * t] = e1;     g_topk_idx[2 * t + 1] = e2;
        g_topk_prob[2 * t] = p[e1] * pr; g_topk_prob[2 * t + 1] = p[e2] * pr;
        atomicAdd(&scnt[e1], 1);
        atomicAdd(&scnt[e2], 1);
    }
    __syncthreads();
    if (tid < NE) {
        atomicAdd(&g_probs_sum[tid], psum[tid]);
        atomicAdd(&g_counts[tid], scnt[tid]);
    }
}

// ---------------- stats + padded segment offsets ----------------
__global__ void k_stats(float* __restrict__ out) {
    if (threadIdx.x == 0) {
        int off = 0;
        for (int e = 0; e < NE; e++) {
            g_poff[e] = off;
            off += ((g_counts[e] + 127) >> 7) << 7;
        }
        g_poff[NE] = off;
        float* tail = out + (size_t)NT * D_MODEL;
        for (int e = 0; e < NE; e++) tail[e] = (float)g_counts[e] / (float)(NT * 2);
        float avg[NE], mean = 0.f;
        for (int e = 0; e < NE; e++) { avg[e] = g_probs_sum[e] / (float)NT; mean += avg[e]; }
        mean /= (float)NE;
        float var = 0.f;
        for (int e = 0; e < NE; e++) { float d = avg[e] - mean; var += d * d; }
        tail[NE] = var / (float)(NE - 1);   // ddof=1
    }
}

// ---------------- scatter slots ----------------
__global__ void k_scatter() {
    int s = blockIdx.x * blockDim.x + threadIdx.x;
    int e = g_topk_idx[s];
    int p = g_poff[e] + atomicAdd(&g_cursor[e], 1);
    g_pos[s] = p;
}

// ---------------- pack: gather x rows into permuted order, tf32-rounded --------
__global__ void __launch_bounds__(256) k_pack(const float* __restrict__ x) {
    int s = blockIdx.x;
    int tok = s >> 1;
    int p = g_pos[s];
    int i = threadIdx.x;
    float4 v = *(const float4*)&x[(size_t)tok * D_MODEL + i * 4];
    *(float4*)&g_xa[(size_t)p * D_MODEL + i * 4] = rna_tf32_4(v);
}

// ---------------- persistent fused dual-GEMM ----------------
// 128x128 block tile, 16-k stages, 3-stage cp.async, warp tile 64x32 (2x4 grid)
// SMEM per stage: A 128x16 @stride20 = 10240B, B 16x128 @stride136 = 8704B
#define A_ST 2560   // floats per A stage
#define B_ST 2176   // floats per B stage
#define SMEM_GEMM ((3 * (A_ST + B_ST)) * 4)   // 56832 bytes

__device__ __forceinline__ void fill_stage(uint32_t aS, uint32_t bS,
                                           const float* __restrict__ A0,
                                           const float* __restrict__ B0,
                                           int koff, int kdim, int ndim, int tid) {
#pragma unroll
    for (int i = 0; i < 2; i++) {               // A: 512 cp16 (128 rows x 4 chunks)
        int id = tid + i * 256;
        int row = id >> 2, q = id & 3;
        cp16(aS + (uint32_t)(row * 20 + q * 4) * 4,
             A0 + (size_t)row * kdim + koff + q * 4);
    }
#pragma unroll
    for (int i = 0; i < 2; i++) {               // B: 512 cp16 (16 k-rows x 32 chunks)
        int id = tid + i * 256;
        int k = id >> 5, ch = id & 31;
        cp16(bS + (uint32_t)(k * 136 + ch * 4) * 4,
             B0 + (size_t)(koff + k) * ndim + ch * 4);
    }
}

__global__ void __launch_bounds__(256, 2) k_moe(const float* __restrict__ w1,
                                                const float* __restrict__ b1,
                                                const float* __restrict__ w2) {
    extern __shared__ float sm[];
    __shared__ int s_tile;
    const int tid = threadIdx.x, lane = tid & 31, warp = tid >> 5;
    const int wm = warp & 1, wn = warp >> 1;
    const int gid = lane >> 2, ktid = lane & 3;
    const uint32_t sb = smem_to_u32(sm);
    const uint32_t aU = sb, bU = sb + 3 * A_ST * 4;
    const int limit = g_poff[NE];

    for (;;) {
        if (tid == 0) s_tile = atomicAdd(&g_cursor2, 1);
        __syncthreads();
        const int t = s_tile;
        __syncthreads();
        if (t >= G1_TILES + G2_TILES) return;

        const bool first = (t < G1_TILES);
        int mblk, n0, kdim, ndim;
        const float* Bbase;
        if (first) { mblk = t >> 5; n0 = (t & 31) << 7; kdim = D_MODEL; ndim = D_FF;    Bbase = w1; }
        else { int t2 = t - G1_TILES; mblk = t2 >> 3; n0 = (t2 & 7) << 7; kdim = D_FF; ndim = D_MODEL; Bbase = w2; }

        const int row0 = mblk << 7;
        if (row0 >= limit) {
            // still signal completion so GEMM2 waiters never hang
            if (first && tid == 0) atomicAdd(&g_done[mblk], 1);
            continue;
        }
        int e = 0;
#pragma unroll
        for (int i = 1; i < NE; i++) if (row0 >= g_poff[i]) e = i;

        if (!first) {
            // wait for all 32 GEMM1 n-tiles of this m-block
            if (tid == 0) {
                while (atomicAdd(&g_done[mblk], 0) < 32) __nanosleep(64);
                __threadfence();
            }
            __syncthreads();
        }

        const float* A0 = (first ? g_xa : g_h) + (size_t)row0 * kdim;
        const float* B0 = Bbase + (size_t)e * kdim * ndim + n0;
        const int NKT = kdim >> 4;

        fill_stage(aU, bU, A0, B0, 0, kdim, ndim, tid);
        CP_COMMIT();
        fill_stage(aU + A_ST * 4, bU + B_ST * 4, A0, B0, 16, kdim, ndim, tid);
        CP_COMMIT();

        float acc[4][4][4];
#pragma unroll
        for (int a = 0; a < 4; a++)
#pragma unroll
            for (int b = 0; b < 4; b++)
#pragma unroll
                for (int c = 0; c < 4; c++) acc[a][b][c] = 0.f;

#pragma unroll 1
        for (int kt = 0; kt < NKT; kt++) {
            CP_WAIT(1);
            __syncthreads();
            const int cn = kt + 2;
            if (cn < NKT) {
                const int s2 = cn % 3;
                fill_stage(aU + s2 * A_ST * 4, bU + s2 * B_ST * 4,
                           A0, B0, cn * 16, kdim, ndim, tid);
            }
            CP_COMMIT();
            const float* Asb = sm + (kt % 3) * A_ST;
            const float* Bsb = sm + 3 * A_ST + (kt % 3) * B_ST;
#pragma unroll
            for (int kk = 0; kk < 16; kk += 8) {
                unsigned a[4][4], b[4][2];
#pragma unroll
                for (int mt = 0; mt < 4; mt++) {
                    int rb_ = wm * 64 + mt * 16;
                    a[mt][0] = __float_as_uint(Asb[(rb_ + gid) * 20 + kk + ktid]);
                    a[mt][1] = __float_as_uint(Asb[(rb_ + gid + 8) * 20 + kk + ktid]);
                    a[mt][2] = __float_as_uint(Asb[(rb_ + gid) * 20 + kk + ktid + 4]);
                    a[mt][3] = __float_as_uint(Asb[(rb_ + gid + 8) * 20 + kk + ktid + 4]);
                }
#pragma unroll
                for (int nt = 0; nt < 4; nt++) {
                    int col = wn * 32 + nt * 8 + gid;
                    b[nt][0] = rna_tf32_u(Bsb[(kk + ktid) * 136 + col]);
                    b[nt][1] = rna_tf32_u(Bsb[(kk + ktid + 4) * 136 + col]);
                }
#pragma unroll
                for (int mt = 0; mt < 4; mt++)
#pragma unroll
                    for (int nt = 0; nt < 4; nt++) mma_tf32(acc[mt][nt], a[mt], b[nt]);
            }
        }

        // epilogue
#pragma unroll
        for (int mt = 0; mt < 4; mt++) {
            int rr0 = row0 + wm * 64 + mt * 16 + gid;
            int rr1 = rr0 + 8;
#pragma unroll
            for (int nt = 0; nt < 4; nt++) {
                int c = n0 + wn * 32 + nt * 8 + ktid * 2;
                float* a = acc[mt][nt];
                if (first) {
                    float bb0 = b1[e * D_FF + c];
                    float bb1 = b1[e * D_FF + c + 1];
                    float2 v0, v1;
                    v0.x = rna_tf32(fmaxf(a[0] + bb0, 0.f));
                    v0.y = rna_tf32(fmaxf(a[1] + bb1, 0.f));
                    v1.x = rna_tf32(fmaxf(a[2] + bb0, 0.f));
                    v1.y = rna_tf32(fmaxf(a[3] + bb1, 0.f));
                    *(float2*)&g_h[(size_t)rr0 * D_FF + c] = v0;
                    *(float2*)&g_h[(size_t)rr1 * D_FF + c] = v1;
                } else {
                    *(float2*)&g_y[(size_t)rr0 * D_MODEL + c] = make_float2(a[0], a[1]);
                    *(float2*)&g_y[(size_t)rr1 * D_MODEL + c] = make_float2(a[2], a[3]);
                }
            }
        }

        if (first) {
            __threadfence();
            __syncthreads();
            if (tid == 0) atomicAdd(&g_done[mblk], 1);
        }
    }
}

// ---------------- combine ----------------
__global__ void __launch_bounds__(256) k_combine(const float* __restrict__ b2,
                                                 float* __restrict__ out) {
    int t = blockIdx.x, i = threadIdx.x;
    int e0 = g_topk_idx[2 * t], e1 = g_topk_idx[2 * t + 1];
    float p0 = g_topk_prob[2 * t], p1 = g_topk_prob[2 * t + 1];
    int q0 = g_pos[2 * t], q1 = g_pos[2 * t + 1];
    float4 y0 = *(const float4*)&g_y[(size_t)q0 * D_MODEL + i * 4];
    float4 y1 = *(const float4*)&g_y[(size_t)q1 * D_MODEL + i * 4];
    float4 c0 = *(const float4*)&b2[(size_t)e0 * D_MODEL + i * 4];
    float4 c1 = *(const float4*)&b2[(size_t)e1 * D_MODEL + i * 4];
    float4 o;
    o.x = p0 * (y0.x + c0.x) + p1 * (y1.x + c1.x);
    o.y = p0 * (y0.y + c0.y) + p1 * (y1.y + c1.y);
    o.z = p0 * (y0.z + c0.z) + p1 * (y1.z + c1.z);
    o.w = p0 * (y0.w + c0.w) + p1 * (y1.w + c1.w);
    *(float4*)&out[(size_t)t * D_MODEL + i * 4] = o;
}

// ---------------- launch ----------------
extern "C" void kernel_launch(void* const* d_in, const int* in_sizes, int n_in,
                              void* d_out, int out_size) {
    (void)in_sizes; (void)n_in; (void)out_size;
    const float* x  = (const float*)d_in[0];
    const float* gw = (const float*)d_in[1];
    const float* gb = (const float*)d_in[2];
    const float* w1 = (const float*)d_in[3];
    const float* b1 = (const float*)d_in[4];
    const float* w2 = (const float*)d_in[5];
    const float* b2 = (const float*)d_in[6];
    float* out = (float*)d_out;

    static int attr_done = 0;
    if (!attr_done) {
        cudaFuncSetAttribute(k_moe, cudaFuncAttributeMaxDynamicSharedMemorySize, SMEM_GEMM);
        attr_done = 1;
    }

    k_init<<<1, 256>>>();
    k_router<<<NT / 8, 256>>>(x, gw, gb);
    k_stats<<<1, 32>>>(out);
    k_scatter<<<(NT * 2) / 256, 256>>>();
    k_pack<<<NT * 2, 256>>>(x);
    k_moe<<<296, 256, SMEM_GEMM>>>(w1, b1, w2);
    k_combine<<<NT, 256>>>(b2, out);
}

// round 12
// speedup vs baseline: 1.1765x; 1.1765x over previous
#include <cuda_runtime.h>
#include <math.h>
#include <stdint.h>

#define D_MODEL 1024
#define D_FF    4096
#define NE      8
#define NT      8192
#define ROWS_MAX 17408
#define NTILES  136             // ROWS_MAX/128 m-tiles

// ---------------- static scratch (no runtime allocation allowed) ----------------
__device__ int   g_topk_idx[NT * 2];
__device__ float g_topk_prob[NT * 2];
__device__ int   g_pos[NT * 2];
__device__ int   g_counts[NE];
__device__ float g_probs_sum[NE];
__device__ int   g_poff[NE + 1];
__device__ int   g_cursor[NE];
__device__ float g_xa[(size_t)ROWS_MAX * D_MODEL];        // permuted + tf32-rounded x
__device__ float g_h[(size_t)ROWS_MAX * D_FF];            // GEMM1 out, tf32-rounded fp32
__device__ float g_y[(size_t)ROWS_MAX * D_MODEL];         // GEMM2 out fp32

// ---------------- PTX helpers (arch-portable only) ----------------
__device__ __forceinline__ uint32_t smem_to_u32(const void* p) {
    uint32_t a;
    asm("{ .reg .u64 t; cvta.to.shared.u64 t, %1; cvt.u32.u64 %0, t; }" : "=r"(a) : "l"(p));
    return a;
}
__device__ __forceinline__ void cp16(uint32_t s, const void* g) {
    asm volatile("cp.async.cg.shared.global [%0], [%1], 16;\n" :: "r"(s), "l"(g) : "memory");
}
#define CP_COMMIT() asm volatile("cp.async.commit_group;\n" ::: "memory")
#define CP_WAIT(n)  asm volatile("cp.async.wait_group %0;\n" :: "n"(n) : "memory")

__device__ __forceinline__ void mma_tf32(float* c, const unsigned* a, const unsigned* b) {
    asm volatile(
        "mma.sync.aligned.m16n8k8.row.col.f32.tf32.tf32.f32 "
        "{%0,%1,%2,%3}, {%4,%5,%6,%7}, {%8,%9}, {%0,%1,%2,%3};\n"
        : "+f"(c[0]), "+f"(c[1]), "+f"(c[2]), "+f"(c[3])
        : "r"(a[0]), "r"(a[1]), "r"(a[2]), "r"(a[3]), "r"(b[0]), "r"(b[1]));
}
__device__ __forceinline__ float rna_tf32(float v) {
    float r;
    asm("cvt.rna.tf32.f32 %0, %1;\n" : "=f"(r) : "f"(v));
    return r;
}
__device__ __forceinline__ unsigned rna_tf32_u(float v) {
    float r;
    asm("cvt.rna.tf32.f32 %0, %1;\n" : "=f"(r) : "f"(v));
    return __float_as_uint(r);
}
__device__ __forceinline__ float4 rna_tf32_4(float4 v) {
    v.x = rna_tf32(v.x); v.y = rna_tf32(v.y);
    v.z = rna_tf32(v.z); v.w = rna_tf32(v.w);
    return v;
}

// ---------------- init ----------------
__global__ void k_init() {
    int i = threadIdx.x;
    if (i < NE) { g_counts[i] = 0; g_probs_sum[i] = 0.f; g_cursor[i] = 0; }
}

// ---------------- router: 1 warp per token ----------------
__global__ void __launch_bounds__(256) k_router(const float* __restrict__ x,
                                                const float* __restrict__ gw,
                                                const float* __restrict__ gb) {
    __shared__ float gws[NE * D_MODEL];
    __shared__ float psum[NE];
    __shared__ int   scnt[NE];
    int tid = threadIdx.x;
    for (int i = tid; i < NE * D_MODEL; i += 256) {
        int d = i >> 3, e = i & 7;
        gws[e * D_MODEL + d] = gw[i];
    }
    if (tid < NE) { psum[tid] = 0.f; scnt[tid] = 0; }
    __syncthreads();

    int lane = tid & 31, warp = tid >> 5;
    int t = blockIdx.x * 8 + warp;
    const float* xr = x + (size_t)t * D_MODEL;

    float acc[NE];
#pragma unroll
    for (int e = 0; e < NE; e++) acc[e] = 0.f;
    for (int i = 0; i < D_MODEL / 32; i++) {
        int d = i * 32 + lane;
        float xv = xr[d];
#pragma unroll
        for (int e = 0; e < NE; e++) acc[e] += xv * gws[e * D_MODEL + d];
    }
#pragma unroll
    for (int e = 0; e < NE; e++)
        for (int off = 16; off > 0; off >>= 1)
            acc[e] += __shfl_xor_sync(0xffffffffu, acc[e], off);

    if (lane == 0) {
        float l[NE], p[NE];
        float m = -1e30f;
#pragma unroll
        for (int e = 0; e < NE; e++) { l[e] = acc[e] + gb[e]; m = fmaxf(m, l[e]); }
        float s = 0.f;
#pragma unroll
        for (int e = 0; e < NE; e++) { p[e] = expf(l[e] - m); s += p[e]; }
        float inv = 1.f / s;
#pragma unroll
        for (int e = 0; e < NE; e++) { p[e] *= inv; atomicAdd(&psum[e], p[e]); }
        int e1 = 0;
#pragma unroll
        for (int e = 1; e < NE; e++) if (p[e] > p[e1]) e1 = e;
        int e2 = -1;
#pragma unroll
        for (int e = 0; e < NE; e++) {
            if (e == e1) continue;
            if (e2 < 0 || p[e] > p[e2]) e2 = e;
        }
        float pr = 1.f / (p[e1] + p[e2]);
        g_topk_idx[2 * t] = e1;     g_topk_idx[2 * t + 1] = e2;
        g_topk_prob[2 * t] = p[e1] * pr; g_topk_prob[2 * t + 1] = p[e2] * pr;
        atomicAdd(&scnt[e1], 1);
        atomicAdd(&scnt[e2], 1);
    }
    __syncthreads();
    if (tid < NE) {
        atomicAdd(&g_probs_sum[tid], psum[tid]);
        atomicAdd(&g_counts[tid], scnt[tid]);
    }
}

// ---------------- stats + padded segment offsets ----------------
__global__ void k_stats(float* __restrict__ out) {
    if (threadIdx.x == 0) {
        int off = 0;
        for (int e = 0; e < NE; e++) {
            g_poff[e] = off;
            off += ((g_counts[e] + 127) >> 7) << 7;
        }
        g_poff[NE] = off;
        float* tail = out + (size_t)NT * D_MODEL;
        for (int e = 0; e < NE; e++) tail[e] = (float)g_counts[e] / (float)(NT * 2);
        float avg[NE], mean = 0.f;
        for (int e = 0; e < NE; e++) { avg[e] = g_probs_sum[e] / (float)NT; mean += avg[e]; }
        mean /= (float)NE;
        float var = 0.f;
        for (int e = 0; e < NE; e++) { float d = avg[e] - mean; var += d * d; }
        tail[NE] = var / (float)(NE - 1);   // ddof=1
    }
}

// ---------------- pack (fused scatter): claim slot, gather + tf32-round row ----
__global__ void __launch_bounds__(256) k_pack(const float* __restrict__ x) {
    __shared__ int s_p;
    int s = blockIdx.x;
    int tok = s >> 1;
    if (threadIdx.x == 0) {
        int e = g_topk_idx[s];
        int p = g_poff[e] + atomicAdd(&g_cursor[e], 1);
        g_pos[s] = p;
        s_p = p;
    }
    __syncthreads();
    int p = s_p;
    int i = threadIdx.x;
    float4 v = *(const float4*)&x[(size_t)tok * D_MODEL + i * 4];
    *(float4*)&g_xa[(size_t)p * D_MODEL + i * 4] = rna_tf32_4(v);
}

// ---------------- tf32 GEMM: 128x128 block, 32-k chunks, 3-stage cp.async ------
// SMEM per stage: A 128x32 @stride36 = 18432B, B 32x128 @stride136 = 17408B
// B is RAW weights; fragments rounded to tf32 in-register (bit-identical, R9/R10)
#define A_ST 4608   // floats per A stage
#define B_ST 4352   // floats per B stage
#define SMEM_GEMM ((3 * (A_ST + B_ST)) * 4)   // 107520 bytes -> 2 CTAs/SM

__device__ __forceinline__ void fill_stage(uint32_t aS, uint32_t bS,
                                           const float* __restrict__ A0,
                                           const float* __restrict__ B0,
                                           int koff, int kdim, int ndim, int tid) {
#pragma unroll
    for (int i = 0; i < 4; i++) {               // A: 1024 cp16 (128 rows x 8 chunks)
        int id = tid + i * 256;
        int row = id >> 3, q = id & 7;
        cp16(aS + (uint32_t)(row * 36 + q * 4) * 4,
             A0 + (size_t)row * kdim + koff + q * 4);
    }
#pragma unroll
    for (int i = 0; i < 4; i++) {               // B: 1024 cp16 (32 k-rows x 32 chunks)
        int id = tid + i * 256;
        int k = id >> 5, ch = id & 31;
        cp16(bS + (uint32_t)(k * 136 + ch * 4) * 4,
             B0 + (size_t)(koff + k) * ndim + ch * 4);
    }
}

template <int KDIM, int NDIM, bool FIRST>
__global__ void __launch_bounds__(256, 2) k_gemm(const float* __restrict__ Bg,
                                                 const float* __restrict__ bias) {
    extern __shared__ float sm[];
    const int row0 = blockIdx.x * 128;
    if (row0 >= g_poff[NE]) return;
    int e = 0;
#pragma unroll
    for (int i = 1; i < NE; i++) if (row0 >= g_poff[i]) e = i;
    const int n0 = blockIdx.y * 128;
    const int tid = threadIdx.x, lane = tid & 31, warp = tid >> 5;
    const int wm = warp & 1, wn = warp >> 1;
    const int gid = lane >> 2, ktid = lane & 3;
    const uint32_t sb = smem_to_u32(sm);
    const uint32_t aU = sb, bU = sb + 3 * A_ST * 4;

    // resolve device symbols IN DEVICE CODE (host symbol decay = garbage ptr)
    const float* A0 = (FIRST ? g_xa : g_h) + (size_t)row0 * KDIM;
    const float* B0 = Bg + (size_t)e * KDIM * NDIM + n0;
    const int NKT = KDIM / 32;

    // prologue: 2 stages in flight
    fill_stage(aU, bU, A0, B0, 0, KDIM, NDIM, tid);
    CP_COMMIT();
    fill_stage(aU + A_ST * 4, bU + B_ST * 4, A0, B0, 32, KDIM, NDIM, tid);
    CP_COMMIT();

    float acc[4][4][4];
#pragma unroll
    for (int a = 0; a < 4; a++)
#pragma unroll
        for (int b = 0; b < 4; b++)
#pragma unroll
            for (int c = 0; c < 4; c++) acc[a][b][c] = 0.f;

#pragma unroll 1
    for (int kt = 0; kt < NKT; kt++) {
        CP_WAIT(1);
        __syncthreads();
        const int cn = kt + 2;
        if (cn < NKT) {
            const int s2 = cn % 3;
            fill_stage(aU + s2 * A_ST * 4, bU + s2 * B_ST * 4,
                       A0, B0, cn * 32, KDIM, NDIM, tid);
        }
        CP_COMMIT();
        const float* Asb = sm + (kt % 3) * A_ST;
        const float* Bsb = sm + 3 * A_ST + (kt % 3) * B_ST;
#pragma unroll
        for (int kk = 0; kk < 32; kk += 8) {
            unsigned a[4][4], b[4][2];
#pragma unroll
            for (int mt = 0; mt < 4; mt++) {
                int rb_ = wm * 64 + mt * 16;
                a[mt][0] = __float_as_uint(Asb[(rb_ + gid) * 36 + kk + ktid]);
                a[mt][1] = __float_as_uint(Asb[(rb_ + gid + 8) * 36 + kk + ktid]);
                a[mt][2] = __float_as_uint(Asb[(rb_ + gid) * 36 + kk + ktid + 4]);
                a[mt][3] = __float_as_uint(Asb[(rb_ + gid + 8) * 36 + kk + ktid + 4]);
            }
#pragma unroll
            for (int nt = 0; nt < 4; nt++) {
                int col = wn * 32 + nt * 8 + gid;
                b[nt][0] = rna_tf32_u(Bsb[(kk + ktid) * 136 + col]);
                b[nt][1] = rna_tf32_u(Bsb[(kk + ktid + 4) * 136 + col]);
            }
#pragma unroll
            for (int mt = 0; mt < 4; mt++)
#pragma unroll
                for (int nt = 0; nt < 4; nt++) mma_tf32(acc[mt][nt], a[mt], b[nt]);
        }
    }

    // epilogue
#pragma unroll
    for (int mt = 0; mt < 4; mt++) {
        int rr0 = row0 + wm * 64 + mt * 16 + gid;
        int rr1 = rr0 + 8;
#pragma unroll
        for (int nt = 0; nt < 4; nt++) {
            int c = n0 + wn * 32 + nt * 8 + ktid * 2;
            float* a = acc[mt][nt];
            if (FIRST) {
                float bb0 = bias[e * NDIM + c];
                float bb1 = bias[e * NDIM + c + 1];
                float2 v0, v1;
                v0.x = rna_tf32(fmaxf(a[0] + bb0, 0.f));
                v0.y = rna_tf32(fmaxf(a[1] + bb1, 0.f));
                v1.x = rna_tf32(fmaxf(a[2] + bb0, 0.f));
                v1.y = rna_tf32(fmaxf(a[3] + bb1, 0.f));
                *(float2*)&g_h[(size_t)rr0 * D_FF + c] = v0;
                *(float2*)&g_h[(size_t)rr1 * D_FF + c] = v1;
            } else {
                *(float2*)&g_y[(size_t)rr0 * D_MODEL + c] = make_float2(a[0], a[1]);
                *(float2*)&g_y[(size_t)rr1 * D_MODEL + c] = make_float2(a[2], a[3]);
            }
        }
    }
}

// ---------------- combine ----------------
__global__ void __launch_bounds__(256) k_combine(const float* __restrict__ b2,
                                                 float* __restrict__ out) {
    int t = blockIdx.x, i = threadIdx.x;
    int e0 = g_topk_idx[2 * t], e1 = g_topk_idx[2 * t + 1];
    float p0 = g_topk_prob[2 * t], p1 = g_topk_prob[2 * t + 1];
    int q0 = g_pos[2 * t], q1 = g_pos[2 * t + 1];
    float4 y0 = *(const float4*)&g_y[(size_t)q0 * D_MODEL + i * 4];
    float4 y1 = *(const float4*)&g_y[(size_t)q1 * D_MODEL + i * 4];
    float4 c0 = *(const float4*)&b2[(size_t)e0 * D_MODEL + i * 4];
    float4 c1 = *(const float4*)&b2[(size_t)e1 * D_MODEL + i * 4];
    float4 o;
    o.x = p0 * (y0.x + c0.x) + p1 * (y1.x + c1.x);
    o.y = p0 * (y0.y + c0.y) + p1 * (y1.y + c1.y);
    o.z = p0 * (y0.z + c0.z) + p1 * (y1.z + c1.z);
    o.w = p0 * (y0.w + c0.w) + p1 * (y1.w + c1.w);
    *(float4*)&out[(size_t)t * D_MODEL + i * 4] = o;
}

// ---------------- launch ----------------
extern "C" void kernel_launch(void* const* d_in, const int* in_sizes, int n_in,
                              void* d_out, int out_size) {
    (void)in_sizes; (void)n_in; (void)out_size;
    const float* x  = (const float*)d_in[0];
    const float* gw = (const float*)d_in[1];
    const float* gb = (const float*)d_in[2];
    const float* w1 = (const float*)d_in[3];
    const float* b1 = (const float*)d_in[4];
    const float* w2 = (const float*)d_in[5];
    const float* b2 = (const float*)d_in[6];
    float* out = (float*)d_out;

    static int attr_done = 0;
    if (!attr_done) {
        cudaFuncSetAttribute(k_gemm<D_MODEL, D_FF, true>,
                             cudaFuncAttributeMaxDynamicSharedMemorySize, SMEM_GEMM);
        cudaFuncSetAttribute(k_gemm<D_FF, D_MODEL, false>,
                             cudaFuncAttributeMaxDynamicSharedMemorySize, SMEM_GEMM);
        attr_done = 1;
    }

    k_init<<<1, 32>>>();
    k_router<<<NT / 8, 256>>>(x, gw, gb);
    k_stats<<<1, 32>>>(out);
    k_pack<<<NT * 2, 256>>>(x);
    k_gemm<D_MODEL, D_FF, true ><<<dim3(NTILES, D_FF / 128), 256, SMEM_GEMM>>>(w1, b1);
    k_gemm<D_FF, D_MODEL, false><<<dim3(NTILES, D_MODEL / 128), 256, SMEM_GEMM>>>(w2, (const float*)0);
    k_combine<<<NT, 256>>>(b2, out);
}

// round 13
// speedup vs baseline: 1.9872x; 1.6892x over previous
#include <cuda_runtime.h>
#include <cuda_fp16.h>
#include <math.h>
#include <stdint.h>

#define D_MODEL 1024
#define D_FF    4096
#define NE      8
#define NT      8192
#define ROWS_MAX 17408
#define NTILES  136             // ROWS_MAX/128 m-tiles

// ---------------- static scratch (no runtime allocation allowed) ----------------
__device__ int    g_topk_idx[NT * 2];
__device__ float  g_topk_prob[NT * 2];
__device__ int    g_pos[NT * 2];
__device__ int    g_counts[NE];
__device__ float  g_probs_sum[NE];
__device__ int    g_poff[NE + 1];
__device__ int    g_cursor[NE];
__device__ __half g_xa[(size_t)ROWS_MAX * D_MODEL];       // permuted fp16 x
__device__ __half g_w1h[(size_t)NE * D_FF * D_MODEL];     // w1^T [e][f][k] fp16
__device__ __half g_w2h[(size_t)NE * D_MODEL * D_FF];     // w2^T [e][d][k] fp16
__device__ __half g_h[(size_t)ROWS_MAX * D_FF];           // GEMM1 out fp16
__device__ float  g_y[(size_t)ROWS_MAX * D_MODEL];        // GEMM2 out fp32

// ---------------- PTX helpers (arch-portable only) ----------------
__device__ __forceinline__ uint32_t smem_to_u32(const void* p) {
    uint32_t a;
    asm("{ .reg .u64 t; cvta.to.shared.u64 t, %1; cvt.u32.u64 %0, t; }" : "=r"(a) : "l"(p));
    return a;
}
__device__ __forceinline__ void cp16(uint32_t s, const void* g) {
    asm volatile("cp.async.cg.shared.global [%0], [%1], 16;\n" :: "r"(s), "l"(g) : "memory");
}
#define CP_COMMIT() asm volatile("cp.async.commit_group;\n" ::: "memory")
#define CP_WAIT(n)  asm volatile("cp.async.wait_group %0;\n" :: "n"(n) : "memory")

// fp16 mma, fp32 accumulate (same 11-bit mantissa as tf32; R5-validated accuracy)
__device__ __forceinline__ void mma_f16(float* c, const unsigned* a, const unsigned* b) {
    asm volatile(
        "mma.sync.aligned.m16n8k16.row.col.f32.f16.f16.f32 "
        "{%0,%1,%2,%3},{%4,%5,%6,%7},{%8,%9},{%0,%1,%2,%3};"
        : "+f"(c[0]), "+f"(c[1]), "+f"(c[2]), "+f"(c[3])
        : "r"(a[0]), "r"(a[1]), "r"(a[2]), "r"(a[3]), "r"(b[0]), "r"(b[1]));
}

// ---------------- init ----------------
__global__ void k_init() {
    int i = threadIdx.x;
    if (i < NE) { g_counts[i] = 0; g_probs_sum[i] = 0.f; g_cursor[i] = 0; }
}

// ---------------- router: 1 warp per token ----------------
__global__ void __launch_bounds__(256) k_router(const float* __restrict__ x,
                                                const float* __restrict__ gw,
                                                const float* __restrict__ gb) {
    __shared__ float gws[NE * D_MODEL];
    __shared__ float psum[NE];
    __shared__ int   scnt[NE];
    int tid = threadIdx.x;
    for (int i = tid; i < NE * D_MODEL; i += 256) {
        int d = i >> 3, e = i & 7;
        gws[e * D_MODEL + d] = gw[i];
    }
    if (tid < NE) { psum[tid] = 0.f; scnt[tid] = 0; }
    __syncthreads();

    int lane = tid & 31, warp = tid >> 5;
    int t = blockIdx.x * 8 + warp;
    const float* xr = x + (size_t)t * D_MODEL;

    float acc[NE];
#pragma unroll
    for (int e = 0; e < NE; e++) acc[e] = 0.f;
    for (int i = 0; i < D_MODEL / 32; i++) {
        int d = i * 32 + lane;
        float xv = xr[d];
#pragma unroll
        for (int e = 0; e < NE; e++) acc[e] += xv * gws[e * D_MODEL + d];
    }
#pragma unroll
    for (int e = 0; e < NE; e++)
        for (int off = 16; off > 0; off >>= 1)
            acc[e] += __shfl_xor_sync(0xffffffffu, acc[e], off);

    if (lane == 0) {
        float l[NE], p[NE];
        float m = -1e30f;
#pragma unroll
        for (int e = 0; e < NE; e++) { l[e] = acc[e] + gb[e]; m = fmaxf(m, l[e]); }
        float s = 0.f;
#pragma unroll
        for (int e = 0; e < NE; e++) { p[e] = expf(l[e] - m); s += p[e]; }
        float inv = 1.f / s;
#pragma unroll
        for (int e = 0; e < NE; e++) { p[e] *= inv; atomicAdd(&psum[e], p[e]); }
        int e1 = 0;
#pragma unroll
        for (int e = 1; e < NE; e++) if (p[e] > p[e1]) e1 = e;
        int e2 = -1;
#pragma unroll
        for (int e = 0; e < NE; e++) {
            if (e == e1) continue;
            if (e2 < 0 || p[e] > p[e2]) e2 = e;
        }
        float pr = 1.f / (p[e1] + p[e2]);
        g_topk_idx[2 * t] = e1;     g_topk_idx[2 * t + 1] = e2;
        g_topk_prob[2 * t] = p[e1] * pr; g_topk_prob[2 * t + 1] = p[e2] * pr;
        atomicAdd(&scnt[e1], 1);
        atomicAdd(&scnt[e2], 1);
    }
    __syncthreads();
    if (tid < NE) {
        atomicAdd(&g_probs_sum[tid], psum[tid]);
        atomicAdd(&g_counts[tid], scnt[tid]);
    }
}

// ---------------- stats + padded segment offsets ----------------
__global__ void k_stats(float* __restrict__ out) {
    if (threadIdx.x == 0) {
        int off = 0;
        for (int e = 0; e < NE; e++) {
            g_poff[e] = off;
            off += ((g_counts[e] + 127) >> 7) << 7;
        }
        g_poff[NE] = off;
        float* tail = out + (size_t)NT * D_MODEL;
        for (int e = 0; e < NE; e++) tail[e] = (float)g_counts[e] / (float)(NT * 2);
        float avg[NE], mean = 0.f;
        for (int e = 0; e < NE; e++) { avg[e] = g_probs_sum[e] / (float)NT; mean += avg[e]; }
        mean /= (float)NE;
        float var = 0.f;
        for (int e = 0; e < NE; e++) { float d = avg[e] - mean; var += d * d; }
        tail[NE] = var / (float)(NE - 1);   // ddof=1
    }
}

// ---------------- pack (fused scatter): claim slot, gather + fp16-convert row --
__global__ void __launch_bounds__(256) k_pack(const float* __restrict__ x) {
    __shared__ int s_p;
    int s = blockIdx.x;
    int tok = s >> 1;
    if (threadIdx.x == 0) {
        int e = g_topk_idx[s];
        int p = g_poff[e] + atomicAdd(&g_cursor[e], 1);
        g_pos[s] = p;
        s_p = p;
    }
    __syncthreads();
    int p = s_p;
    int i = threadIdx.x;
    float4 v = *(const float4*)&x[(size_t)tok * D_MODEL + i * 4];
    __half2* d = (__half2*)&g_xa[(size_t)p * D_MODEL + i * 4];
    d[0] = __floats2half2_rn(v.x, v.y);
    d[1] = __floats2half2_rn(v.z, v.w);
}

// ---------------- weight transpose to K-major fp16 (R5-proven) -----------------
// src fp32 [e][R][C] -> dst fp16 [e][C][R]
template <int R, int C>
__global__ void __launch_bounds__(256) k_transpose(const float* __restrict__ src,
                                                   __half* __restrict__ dst) {
    __shared__ float t[32][33];
    int e = blockIdx.z;
    const float* s = src + (size_t)e * R * C;
    __half* d = dst + (size_t)e * R * C;
    int c0 = blockIdx.x * 32, r0 = blockIdx.y * 32;
#pragma unroll
    for (int j = 0; j < 32; j += 8)
        t[threadIdx.y + j][threadIdx.x] =
            s[(size_t)(r0 + threadIdx.y + j) * C + c0 + threadIdx.x];
    __syncthreads();
#pragma unroll
    for (int j = 0; j < 32; j += 8)
        d[(size_t)(c0 + threadIdx.y + j) * R + r0 + threadIdx.x] =
            __float2half_rn(t[threadIdx.x][threadIdx.y + j]);
}

// ---------------- fp16 GEMM: 128x128 block, 64-k chunks, 3-stage cp.async ------
// A stage: 128 rows x 72 halves (ldA=72 -> conflict-free scalar LDS), 18432B
// B stage: 128 n-rows x 72 halves (weights pre-transposed [e][n][k]),  18432B
#define A_STH 9216                         // halves per A stage
#define ST_BYTES (2 * A_STH * 2)           // 36864 bytes per stage
#define SMEM_GEMM (3 * ST_BYTES)           // 110592 -> 2 CTAs/SM

__device__ __forceinline__ void fill_stage(uint32_t aS, uint32_t bS,
                                           const __half* __restrict__ A0,
                                           const __half* __restrict__ B0,
                                           int koff, int kdim, int tid) {
#pragma unroll
    for (int i = 0; i < 4; i++) {          // A: 1024 cp16 (128 rows x 8 chunks)
        int id = tid + i * 256;
        int row = id >> 3, ch = id & 7;
        cp16(aS + (uint32_t)(row * 144 + ch * 16),
             A0 + (size_t)row * kdim + koff + ch * 8);
    }
#pragma unroll
    for (int i = 0; i < 4; i++) {          // B: 1024 cp16 (128 n-rows x 8 chunks)
        int id = tid + i * 256;
        int row = id >> 3, ch = id & 7;
        cp16(bS + (uint32_t)(row * 144 + ch * 16),
             B0 + (size_t)row * kdim + koff + ch * 8);
    }
}

template <int KDIM, int NDIM, bool FIRST>
__global__ void __launch_bounds__(256, 2) k_gemm(const __half* __restrict__ Bg,
                                                 const float* __restrict__ bias) {
    extern __shared__ char smc[];
    const int row0 = blockIdx.x * 128;
    if (row0 >= g_poff[NE]) return;
    int e = 0;
#pragma unroll
    for (int i = 1; i < NE; i++) if (row0 >= g_poff[i]) e = i;
    const int n0 = blockIdx.y * 128;
    const int tid = threadIdx.x, lane = tid & 31, warp = tid >> 5;
    const int wm = warp & 1, wn = warp >> 1;
    const int gid = lane >> 2, ktid = lane & 3;
    const uint32_t sb = smem_to_u32(smc);

    // resolve device symbols IN DEVICE CODE
    const __half* A0 = (FIRST ? g_xa : g_h) + (size_t)row0 * KDIM;
    const __half* B0 = Bg + (size_t)e * KDIM * NDIM + (size_t)n0 * KDIM;
    const int NKT = KDIM / 64;

    // prologue: 2 stages in flight
    fill_stage(sb, sb + A_STH * 2, A0, B0, 0, KDIM, tid);
    CP_COMMIT();
    fill_stage(sb + ST_BYTES, sb + ST_BYTES + A_STH * 2, A0, B0, 64, KDIM, tid);
    CP_COMMIT();

    float acc[4][4][4];
#pragma unroll
    for (int a = 0; a < 4; a++)
#pragma unroll
        for (int b = 0; b < 4; b++)
#pragma unroll
            for (int c = 0; c < 4; c++) acc[a][b][c] = 0.f;

#pragma unroll 1
    for (int kt = 0; kt < NKT; kt++) {
        CP_WAIT(1);
        __syncthreads();
        const int cn = kt + 2;
        if (cn < NKT) {
            const uint32_t s2 = sb + (uint32_t)(cn % 3) * ST_BYTES;
            fill_stage(s2, s2 + A_STH * 2, A0, B0, cn * 64, KDIM, tid);
        }
        CP_COMMIT();
        const uint32_t* Aw = (const uint32_t*)(smc + (kt % 3) * ST_BYTES);
        const uint32_t* Bw = Aw + A_STH / 2;     // 4608 words
#pragma unroll
        for (int kk = 0; kk < 4; kk++) {         // 4 x k16
            const int kkw = kk * 8;
            unsigned a[4][4], b[4][2];
#pragma unroll
            for (int mt = 0; mt < 4; mt++) {
                int rb_ = wm * 64 + mt * 16;
                a[mt][0] = Aw[(rb_ + gid) * 36 + kkw + ktid];
                a[mt][1] = Aw[(rb_ + gid + 8) * 36 + kkw + ktid];
                a[mt][2] = Aw[(rb_ + gid) * 36 + kkw + ktid + 4];
                a[mt][3] = Aw[(rb_ + gid + 8) * 36 + kkw + ktid + 4];
            }
#pragma unroll
            for (int nt = 0; nt < 4; nt++) {
                int cr = wn * 32 + nt * 8 + gid;
                b[nt][0] = Bw[cr * 36 + kkw + ktid];
                b[nt][1] = Bw[cr * 36 + kkw + ktid + 4];
            }
#pragma unroll
            for (int mt = 0; mt < 4; mt++)
#pragma unroll
                for (int nt = 0; nt < 4; nt++) mma_f16(acc[mt][nt], a[mt], b[nt]);
        }
    }

    // epilogue (C layout of m16n8k16 == m16n8k8: rows gid/gid+8, cols 2ktid,2ktid+1)
#pragma unroll
    for (int mt = 0; mt < 4; mt++) {
        int rr0 = row0 + wm * 64 + mt * 16 + gid;
        int rr1 = rr0 + 8;
#pragma unroll
        for (int nt = 0; nt < 4; nt++) {
            int c = n0 + wn * 32 + nt * 8 + ktid * 2;
            float* a = acc[mt][nt];
            if (FIRST) {
                float bb0 = bias[e * NDIM + c];
                float bb1 = bias[e * NDIM + c + 1];
                __half2 h0 = __floats2half2_rn(fmaxf(a[0] + bb0, 0.f),
                                               fmaxf(a[1] + bb1, 0.f));
                __half2 h1 = __floats2half2_rn(fmaxf(a[2] + bb0, 0.f),
                                               fmaxf(a[3] + bb1, 0.f));
                *(__half2*)&g_h[(size_t)rr0 * D_FF + c] = h0;
                *(__half2*)&g_h[(size_t)rr1 * D_FF + c] = h1;
            } else {
                *(float2*)&g_y[(size_t)rr0 * D_MODEL + c] = make_float2(a[0], a[1]);
                *(float2*)&g_y[(size_t)rr1 * D_MODEL + c] = make_float2(a[2], a[3]);
            }
        }
    }
}

// ---------------- combine ----------------
__global__ void __launch_bounds__(256) k_combine(const float* __restrict__ b2,
                                                 float* __restrict__ out) {
    int t = blockIdx.x, i = threadIdx.x;
    int e0 = g_topk_idx[2 * t], e1 = g_topk_idx[2 * t + 1];
    float p0 = g_topk_prob[2 * t], p1 = g_topk_prob[2 * t + 1];
    int q0 = g_pos[2 * t], q1 = g_pos[2 * t + 1];
    float4 y0 = *(const float4*)&g_y[(size_t)q0 * D_MODEL + i * 4];
    float4 y1 = *(const float4*)&g_y[(size_t)q1 * D_MODEL + i * 4];
    float4 c0 = *(const float4*)&b2[(size_t)e0 * D_MODEL + i * 4];
    float4 c1 = *(const float4*)&b2[(size_t)e1 * D_MODEL + i * 4];
    float4 o;
    o.x = p0 * (y0.x + c0.x) + p1 * (y1.x + c1.x);
    o.y = p0 * (y0.y + c0.y) + p1 * (y1.y + c1.y);
    o.z = p0 * (y0.z + c0.z) + p1 * (y1.z + c1.z);
    o.w = p0 * (y0.w + c0.w) + p1 * (y1.w + c1.w);
    *(float4*)&out[(size_t)t * D_MODEL + i * 4] = o;
}

// ---------------- launch ----------------
extern "C" void kernel_launch(void* const* d_in, const int* in_sizes, int n_in,
                              void* d_out, int out_size) {
    (void)in_sizes; (void)n_in; (void)out_size;
    const float* x  = (const float*)d_in[0];
    const float* gw = (const float*)d_in[1];
    const float* gb = (const float*)d_in[2];
    const float* w1 = (const float*)d_in[3];
    const float* b1 = (const float*)d_in[4];
    const float* w2 = (const float*)d_in[5];
    const float* b2 = (const float*)d_in[6];
    float* out = (float*)d_out;

    static int attr_done = 0;
    if (!attr_done) {
        cudaFuncSetAttribute(k_gemm<D_MODEL, D_FF, true>,
                             cudaFuncAttributeMaxDynamicSharedMemorySize, SMEM_GEMM);
        cudaFuncSetAttribute(k_gemm<D_FF, D_MODEL, false>,
                             cudaFuncAttributeMaxDynamicSharedMemorySize, SMEM_GEMM);
        attr_done = 1;
    }

    __half* w1h; cudaGetSymbolAddress((void**)&w1h, g_w1h);
    __half* w2h; cudaGetSymbolAddress((void**)&w2h, g_w2h);

    k_init<<<1, 32>>>();
    k_router<<<NT / 8, 256>>>(x, gw, gb);
    k_stats<<<1, 32>>>(out);
    k_pack<<<NT * 2, 256>>>(x);
    k_transpose<D_MODEL, D_FF><<<dim3(D_FF / 32, D_MODEL / 32, NE), dim3(32, 8)>>>(w1, w1h);
    k_transpose<D_FF, D_MODEL><<<dim3(D_MODEL / 32, D_FF / 32, NE), dim3(32, 8)>>>(w2, w2h);
    k_gemm<D_MODEL, D_FF, true ><<<dim3(NTILES, D_FF / 128), 256, SMEM_GEMM>>>(w1h, b1);
    k_gemm<D_FF, D_MODEL, false><<<dim3(NTILES, D_MODEL / 128), 256, SMEM_GEMM>>>(w2h, (const float*)0);
    k_combine<<<NT, 256>>>(b2, out);
}

// round 14
// speedup vs baseline: 2.0050x; 1.0089x over previous
#include <cuda_runtime.h>
#include <cuda_fp16.h>
#include <math.h>
#include <stdint.h>

#define D_MODEL 1024
#define D_FF    4096
#define NE      8
#define NT      8192
#define ROWS_MAX 17408
#define NTILES  136             // ROWS_MAX/128 m-tiles

// ---------------- static scratch (no runtime allocation allowed) ----------------
__device__ int    g_topk_idx[NT * 2];
__device__ float  g_topk_prob[NT * 2];
__device__ int    g_pos[NT * 2];
__device__ int    g_counts[NE];
__device__ float  g_probs_sum[NE];
__device__ int    g_poff[NE + 1];
__device__ int    g_cursor[NE];
__device__ __half g_xa[(size_t)ROWS_MAX * D_MODEL];       // permuted fp16 x
__device__ __half g_w1h[(size_t)NE * D_FF * D_MODEL];     // w1^T [e][f][k] fp16
__device__ __half g_w2h[(size_t)NE * D_MODEL * D_FF];     // w2^T [e][d][k] fp16
__device__ __half g_h[(size_t)ROWS_MAX * D_FF];           // GEMM1 out fp16
__device__ float  g_y[(size_t)ROWS_MAX * D_MODEL];        // GEMM2 out fp32

// ---------------- PTX helpers (arch-portable only) ----------------
__device__ __forceinline__ uint32_t smem_to_u32(const void* p) {
    uint32_t a;
    asm("{ .reg .u64 t; cvta.to.shared.u64 t, %1; cvt.u32.u64 %0, t; }" : "=r"(a) : "l"(p));
    return a;
}
__device__ __forceinline__ void cp16(uint32_t s, const void* g) {
    asm volatile("cp.async.cg.shared.global [%0], [%1], 16;\n" :: "r"(s), "l"(g) : "memory");
}
#define CP_COMMIT() asm volatile("cp.async.commit_group;\n" ::: "memory")
#define CP_WAIT(n)  asm volatile("cp.async.wait_group %0;\n" :: "n"(n) : "memory")

// fp16 mma, fp32 accumulate (same 11-bit mantissa as tf32; R5/R13-validated)
__device__ __forceinline__ void mma_f16(float* c, const unsigned* a, const unsigned* b) {
    asm volatile(
        "mma.sync.aligned.m16n8k16.row.col.f32.f16.f16.f32 "
        "{%0,%1,%2,%3},{%4,%5,%6,%7},{%8,%9},{%0,%1,%2,%3};"
        : "+f"(c[0]), "+f"(c[1]), "+f"(c[2]), "+f"(c[3])
        : "r"(a[0]), "r"(a[1]), "r"(a[2]), "r"(a[3]), "r"(b[0]), "r"(b[1]));
}

// ---------------- init ----------------
__global__ void k_init() {
    int i = threadIdx.x;
    if (i < NE) { g_counts[i] = 0; g_probs_sum[i] = 0.f; g_cursor[i] = 0; }
}

// ---------------- router: 1 warp per token ----------------
__global__ void __launch_bounds__(256) k_router(const float* __restrict__ x,
                                                const float* __restrict__ gw,
                                                const float* __restrict__ gb) {
    __shared__ float gws[NE * D_MODEL];
    __shared__ float psum[NE];
    __shared__ int   scnt[NE];
    int tid = threadIdx.x;
    for (int i = tid; i < NE * D_MODEL; i += 256) {
        int d = i >> 3, e = i & 7;
        gws[e * D_MODEL + d] = gw[i];
    }
    if (tid < NE) { psum[tid] = 0.f; scnt[tid] = 0; }
    __syncthreads();

    int lane = tid & 31, warp = tid >> 5;
    int t = blockIdx.x * 8 + warp;
    const float* xr = x + (size_t)t * D_MODEL;

    float acc[NE];
#pragma unroll
    for (int e = 0; e < NE; e++) acc[e] = 0.f;
    for (int i = 0; i < D_MODEL / 32; i++) {
        int d = i * 32 + lane;
        float xv = xr[d];
#pragma unroll
        for (int e = 0; e < NE; e++) acc[e] += xv * gws[e * D_MODEL + d];
    }
#pragma unroll
    for (int e = 0; e < NE; e++)
        for (int off = 16; off > 0; off >>= 1)
            acc[e] += __shfl_xor_sync(0xffffffffu, acc[e], off);

    if (lane == 0) {
        float l[NE], p[NE];
        float m = -1e30f;
#pragma unroll
        for (int e = 0; e < NE; e++) { l[e] = acc[e] + gb[e]; m = fmaxf(m, l[e]); }
        float s = 0.f;
#pragma unroll
        for (int e = 0; e < NE; e++) { p[e] = expf(l[e] - m); s += p[e]; }
        float inv = 1.f / s;
#pragma unroll
        for (int e = 0; e < NE; e++) { p[e] *= inv; atomicAdd(&psum[e], p[e]); }
        int e1 = 0;
#pragma unroll
        for (int e = 1; e < NE; e++) if (p[e] > p[e1]) e1 = e;
        int e2 = -1;
#pragma unroll
        for (int e = 0; e < NE; e++) {
            if (e == e1) continue;
            if (e2 < 0 || p[e] > p[e2]) e2 = e;
        }
        float pr = 1.f / (p[e1] + p[e2]);
        g_topk_idx[2 * t] = e1;     g_topk_idx[2 * t + 1] = e2;
        g_topk_prob[2 * t] = p[e1] * pr; g_topk_prob[2 * t + 1] = p[e2] * pr;
        atomicAdd(&scnt[e1], 1);
        atomicAdd(&scnt[e2], 1);
    }
    __syncthreads();
    if (tid < NE) {
        atomicAdd(&g_probs_sum[tid], psum[tid]);
        atomicAdd(&g_counts[tid], scnt[tid]);
    }
}

// ---------------- stats + padded segment offsets ----------------
__global__ void k_stats(float* __restrict__ out) {
    if (threadIdx.x == 0) {
        int off = 0;
        for (int e = 0; e < NE; e++) {
            g_poff[e] = off;
            off += ((g_counts[e] + 127) >> 7) << 7;
        }
        g_poff[NE] = off;
        float* tail = out + (size_t)NT * D_MODEL;
        for (int e = 0; e < NE; e++) tail[e] = (float)g_counts[e] / (float)(NT * 2);
        float avg[NE], mean = 0.f;
        for (int e = 0; e < NE; e++) { avg[e] = g_probs_sum[e] / (float)NT; mean += avg[e]; }
        mean /= (float)NE;
        float var = 0.f;
        for (int e = 0; e < NE; e++) { float d = avg[e] - mean; var += d * d; }
        tail[NE] = var / (float)(NE - 1);   // ddof=1
    }
}

// ---------------- pack (fused scatter): claim slot, gather + fp16-convert row --
__global__ void __launch_bounds__(256) k_pack(const float* __restrict__ x) {
    __shared__ int s_p;
    int s = blockIdx.x;
    int tok = s >> 1;
    if (threadIdx.x == 0) {
        int e = g_topk_idx[s];
        int p = g_poff[e] + atomicAdd(&g_cursor[e], 1);
        g_pos[s] = p;
        s_p = p;
    }
    __syncthreads();
    int p = s_p;
    int i = threadIdx.x;
    float4 v = *(const float4*)&x[(size_t)tok * D_MODEL + i * 4];
    __half2* d = (__half2*)&g_xa[(size_t)p * D_MODEL + i * 4];
    d[0] = __floats2half2_rn(v.x, v.y);
    d[1] = __floats2half2_rn(v.z, v.w);
}

// ---------------- weight transpose to K-major fp16 -----------------
template <int R, int C>
__global__ void __launch_bounds__(256) k_transpose(const float* __restrict__ src,
                                                   __half* __restrict__ dst) {
    __shared__ float t[32][33];
    int e = blockIdx.z;
    const float* s = src + (size_t)e * R * C;
    __half* d = dst + (size_t)e * R * C;
    int c0 = blockIdx.x * 32, r0 = blockIdx.y * 32;
#pragma unroll
    for (int j = 0; j < 32; j += 8)
        t[threadIdx.y + j][threadIdx.x] =
            s[(size_t)(r0 + threadIdx.y + j) * C + c0 + threadIdx.x];
    __syncthreads();
#pragma unroll
    for (int j = 0; j < 32; j += 8)
        d[(size_t)(c0 + threadIdx.y + j) * R + r0 + threadIdx.x] =
            __float2half_rn(t[threadIdx.x][threadIdx.y + j]);
}

// ---------------- fp16 GEMM: 128x128 block, 64-k chunks, 3-stage cp.async ------
// A stage: 128 rows x 72 halves (ldA=72 -> conflict-free scalar LDS), 18432B
// B stage: 128 n-rows x 72 halves (weights pre-transposed [e][n][k]),  18432B
// Inner kt body: explicit fragment double-buffer (LDS of kk+1 overlaps mma of kk)
#define A_STH 9216                         // halves per A stage
#define ST_BYTES (2 * A_STH * 2)           // 36864 bytes per stage
#define SMEM_GEMM (3 * ST_BYTES)           // 110592 -> 2 CTAs/SM

__device__ __forceinline__ void fill_stage(uint32_t aS, uint32_t bS,
                                           const __half* __restrict__ A0,
                                           const __half* __restrict__ B0,
                                           int koff, int kdim, int tid) {
#pragma unroll
    for (int i = 0; i < 4; i++) {          // A: 1024 cp16 (128 rows x 8 chunks)
        int id = tid + i * 256;
        int row = id >> 3, ch = id & 7;
        cp16(aS + (uint32_t)(row * 144 + ch * 16),
             A0 + (size_t)row * kdim + koff + ch * 8);
    }
#pragma unroll
    for (int i = 0; i < 4; i++) {          // B: 1024 cp16 (128 n-rows x 8 chunks)
        int id = tid + i * 256;
        int row = id >> 3, ch = id & 7;
        cp16(bS + (uint32_t)(row * 144 + ch * 16),
             B0 + (size_t)row * kdim + koff + ch * 8);
    }
}

template <int KDIM, int NDIM, bool FIRST>
__global__ void __launch_bounds__(256, 2) k_gemm(const __half* __restrict__ Bg,
                                                 const float* __restrict__ bias) {
    extern __shared__ char smc[];
    const int row0 = blockIdx.x * 128;
    if (row0 >= g_poff[NE]) return;
    int e = 0;
#pragma unroll
    for (int i = 1; i < NE; i++) if (row0 >= g_poff[i]) e = i;
    const int n0 = blockIdx.y * 128;
    const int tid = threadIdx.x, lane = tid & 31, warp = tid >> 5;
    const int wm = warp & 1, wn = warp >> 1;
    const int gid = lane >> 2, ktid = lane & 3;
    const uint32_t sb = smem_to_u32(smc);

    // resolve device symbols IN DEVICE CODE
    const __half* A0 = (FIRST ? g_xa : g_h) + (size_t)row0 * KDIM;
    const __half* B0 = Bg + (size_t)e * KDIM * NDIM + (size_t)n0 * KDIM;
    const int NKT = KDIM / 64;

    // prologue: 2 stages in flight
    fill_stage(sb, sb + A_STH * 2, A0, B0, 0, KDIM, tid);
    CP_COMMIT();
    fill_stage(sb + ST_BYTES, sb + ST_BYTES + A_STH * 2, A0, B0, 64, KDIM, tid);
    CP_COMMIT();

    float acc[4][4][4];
#pragma unroll
    for (int a = 0; a < 4; a++)
#pragma unroll
        for (int b = 0; b < 4; b++)
#pragma unroll
            for (int c = 0; c < 4; c++) acc[a][b][c] = 0.f;

    // per-thread fragment base offsets (words)
    const int aBase0 = (wm * 64 + gid) * 36 + ktid;          // + mt*16*36 + kkw(+4)
    const int bBase0 = (wn * 32 + gid) * 36 + ktid;          // + nt*8*36  + kkw(+4)

#pragma unroll 1
    for (int kt = 0; kt < NKT; kt++) {
        CP_WAIT(1);
        __syncthreads();
        const int cn = kt + 2;
        if (cn < NKT) {
            const uint32_t s2 = sb + (uint32_t)(cn % 3) * ST_BYTES;
            fill_stage(s2, s2 + A_STH * 2, A0, B0, cn * 64, KDIM, tid);
        }
        CP_COMMIT();
        const uint32_t* Aw = (const uint32_t*)(smc + (kt % 3) * ST_BYTES);
        const uint32_t* Bw = Aw + A_STH / 2;     // 4608 words

        unsigned a[2][4][4], b[2][4][2];
        // preload kk = 0 fragments
#pragma unroll
        for (int mt = 0; mt < 4; mt++) {
            int base = aBase0 + mt * (16 * 36);
            a[0][mt][0] = Aw[base];
            a[0][mt][1] = Aw[base + 8 * 36];
            a[0][mt][2] = Aw[base + 4];
            a[0][mt][3] = Aw[base + 8 * 36 + 4];
        }
#pragma unroll
        for (int nt = 0; nt < 4; nt++) {
            int base = bBase0 + nt * (8 * 36);
            b[0][nt][0] = Bw[base];
            b[0][nt][1] = Bw[base + 4];
        }
#pragma unroll
        for (int kk = 0; kk < 4; kk++) {
            const int cur = kk & 1, nxt = cur ^ 1;
            if (kk < 3) {
                const int kkw = (kk + 1) * 8;
#pragma unroll
                for (int mt = 0; mt < 4; mt++) {
                    int base = aBase0 + mt * (16 * 36) + kkw;
                    a[nxt][mt][0] = Aw[base];
                    a[nxt][mt][1] = Aw[base + 8 * 36];
                    a[nxt][mt][2] = Aw[base + 4];
                    a[nxt][mt][3] = Aw[base + 8 * 36 + 4];
                }
#pragma unroll
                for (int nt = 0; nt < 4; nt++) {
                    int base = bBase0 + nt * (8 * 36) + kkw;
                    b[nxt][nt][0] = Bw[base];
                    b[nxt][nt][1] = Bw[base + 4];
                }
            }
#pragma unroll
            for (int mt = 0; mt < 4; mt++)
#pragma unroll
                for (int nt = 0; nt < 4; nt++)
                    mma_f16(acc[mt][nt], a[cur][mt], b[cur][nt]);
        }
    }

    // epilogue
#pragma unroll
    for (int mt = 0; mt < 4; mt++) {
        int rr0 = row0 + wm * 64 + mt * 16 + gid;
        int rr1 = rr0 + 8;
#pragma unroll
        for (int nt = 0; nt < 4; nt++) {
            int c = n0 + wn * 32 + nt * 8 + ktid * 2;
            float* a = acc[mt][nt];
            if (FIRST) {
                float bb0 = bias[e * NDIM + c];
                float bb1 = bias[e * NDIM + c + 1];
                __half2 h0 = __floats2half2_rn(fmaxf(a[0] + bb0, 0.f),
                                               fmaxf(a[1] + bb1, 0.f));
                __half2 h1 = __floats2half2_rn(fmaxf(a[2] + bb0, 0.f),
                                               fmaxf(a[3] + bb1, 0.f));
                *(__half2*)&g_h[(size_t)rr0 * D_FF + c] = h0;
                *(__half2*)&g_h[(size_t)rr1 * D_FF + c] = h1;
            } else {
                *(float2*)&g_y[(size_t)rr0 * D_MODEL + c] = make_float2(a[0], a[1]);
                *(float2*)&g_y[(size_t)rr1 * D_MODEL + c] = make_float2(a[2], a[3]);
            }
        }
    }
}

// ---------------- combine ----------------
__global__ void __launch_bounds__(256) k_combine(const float* __restrict__ b2,
                                                 float* __restrict__ out) {
    int t = blockIdx.x, i = threadIdx.x;
    int e0 = g_topk_idx[2 * t], e1 = g_topk_idx[2 * t + 1];
    float p0 = g_topk_prob[2 * t], p1 = g_topk_prob[2 * t + 1];
    int q0 = g_pos[2 * t], q1 = g_pos[2 * t + 1];
    float4 y0 = *(const float4*)&g_y[(size_t)q0 * D_MODEL + i * 4];
    float4 y1 = *(const float4*)&g_y[(size_t)q1 * D_MODEL + i * 4];
    float4 c0 = *(const float4*)&b2[(size_t)e0 * D_MODEL + i * 4];
    float4 c1 = *(const float4*)&b2[(size_t)e1 * D_MODEL + i * 4];
    float4 o;
    o.x = p0 * (y0.x + c0.x) + p1 * (y1.x + c1.x);
    o.y = p0 * (y0.y + c0.y) + p1 * (y1.y + c1.y);
    o.z = p0 * (y0.z + c0.z) + p1 * (y1.z + c1.z);
    o.w = p0 * (y0.w + c0.w) + p1 * (y1.w + c1.w);
    *(float4*)&out[(size_t)t * D_MODEL + i * 4] = o;
}

// ---------------- launch ----------------
extern "C" void kernel_launch(void* const* d_in, const int* in_sizes, int n_in,
                              void* d_out, int out_size) {
    (void)in_sizes; (void)n_in; (void)out_size;
    const float* x  = (const float*)d_in[0];
    const float* gw = (const float*)d_in[1];
    const float* gb = (const float*)d_in[2];
    const float* w1 = (const float*)d_in[3];
    const float* b1 = (const float*)d_in[4];
    const float* w2 = (const float*)d_in[5];
    const float* b2 = (const float*)d_in[6];
    float* out = (float*)d_out;

    static int attr_done = 0;
    if (!attr_done) {
        cudaFuncSetAttribute(k_gemm<D_MODEL, D_FF, true>,
                             cudaFuncAttributeMaxDynamicSharedMemorySize, SMEM_GEMM);
        cudaFuncSetAttribute(k_gemm<D_FF, D_MODEL, false>,
                             cudaFuncAttributeMaxDynamicSharedMemorySize, SMEM_GEMM);
        attr_done = 1;
    }

    __half* w1h; cudaGetSymbolAddress((void**)&w1h, g_w1h);
    __half* w2h; cudaGetSymbolAddress((void**)&w2h, g_w2h);

    k_init<<<1, 32>>>();
    k_router<<<NT / 8, 256>>>(x, gw, gb);
    k_stats<<<1, 32>>>(out);
    k_pack<<<NT * 2, 256>>>(x);
    k_transpose<D_MODEL, D_FF><<<dim3(D_FF / 32, D_MODEL / 32, NE), dim3(32, 8)>>>(w1, w1h);
    k_transpose<D_FF, D_MODEL><<<dim3(D_MODEL / 32, D_FF / 32, NE), dim3(32, 8)>>>(w2, w2h);
    k_gemm<D_MODEL, D_FF, true ><<<dim3(NTILES, D_FF / 128), 256, SMEM_GEMM>>>(w1h, b1);
    k_gemm<D_FF, D_MODEL, false><<<dim3(NTILES, D_MODEL / 128), 256, SMEM_GEMM>>>(w2h, (const float*)0);
    k_combine<<<NT, 256>>>(b2, out);
}

// round 15
// speedup vs baseline: 2.0419x; 1.0184x over previous
#include <cuda_runtime.h>
#include <cuda_fp16.h>
#include <math.h>
#include <stdint.h>

#define D_MODEL 1024
#define D_FF    4096
#define NE      8
#define NT      8192
#define ROWS_MAX 17408
#define NTILES  136             // ROWS_MAX/128 m-tiles

// ---------------- static scratch (no runtime allocation allowed) ----------------
__device__ int    g_topk_idx[NT * 2];
__device__ float  g_topk_prob[NT * 2];
__device__ int    g_pos[NT * 2];
__device__ int    g_counts[NE];
__device__ float  g_probs_sum[NE];
__device__ int    g_poff[NE + 1];
__device__ int    g_cursor[NE];
__device__ __half g_xa[(size_t)ROWS_MAX * D_MODEL];       // permuted fp16 x
__device__ __half g_w1h[(size_t)NE * D_FF * D_MODEL];     // w1^T [e][f][k] fp16
__device__ __half g_w2h[(size_t)NE * D_MODEL * D_FF];     // w2^T [e][d][k] fp16
__device__ __half g_h[(size_t)ROWS_MAX * D_FF];           // GEMM1 out fp16
__device__ float  g_y[(size_t)ROWS_MAX * D_MODEL];        // GEMM2 out fp32

// ---------------- PTX helpers (arch-portable only) ----------------
__device__ __forceinline__ uint32_t smem_to_u32(const void* p) {
    uint32_t a;
    asm("{ .reg .u64 t; cvta.to.shared.u64 t, %1; cvt.u32.u64 %0, t; }" : "=r"(a) : "l"(p));
    return a;
}
__device__ __forceinline__ void cp16(uint32_t s, const void* g) {
    asm volatile("cp.async.cg.shared.global [%0], [%1], 16;\n" :: "r"(s), "l"(g) : "memory");
}
#define CP_COMMIT() asm volatile("cp.async.commit_group;\n" ::: "memory")
#define CP_WAIT(n)  asm volatile("cp.async.wait_group %0;\n" :: "n"(n) : "memory")

// fp16 mma, fp32 accumulate (same 11-bit mantissa as tf32; R5/R13-validated)
__device__ __forceinline__ void mma_f16(float* c, const unsigned* a, const unsigned* b) {
    asm volatile(
        "mma.sync.aligned.m16n8k16.row.col.f32.f16.f16.f32 "
        "{%0,%1,%2,%3},{%4,%5,%6,%7},{%8,%9},{%0,%1,%2,%3};"
        : "+f"(c[0]), "+f"(c[1]), "+f"(c[2]), "+f"(c[3])
        : "r"(a[0]), "r"(a[1]), "r"(a[2]), "r"(a[3]), "r"(b[0]), "r"(b[1]));
}

// ---------------- init ----------------
__global__ void k_init() {
    int i = threadIdx.x;
    if (i < NE) { g_counts[i] = 0; g_probs_sum[i] = 0.f; g_cursor[i] = 0; }
}

// ---------------- router: 1 warp per token ----------------
__global__ void __launch_bounds__(256) k_router(const float* __restrict__ x,
                                                const float* __restrict__ gw,
                                                const float* __restrict__ gb) {
    __shared__ float gws[NE * D_MODEL];
    __shared__ float psum[NE];
    __shared__ int   scnt[NE];
    int tid = threadIdx.x;
    for (int i = tid; i < NE * D_MODEL; i += 256) {
        int d = i >> 3, e = i & 7;
        gws[e * D_MODEL + d] = gw[i];
    }
    if (tid < NE) { psum[tid] = 0.f; scnt[tid] = 0; }
    __syncthreads();

    int lane = tid & 31, warp = tid >> 5;
    int t = blockIdx.x * 8 + warp;
    const float* xr = x + (size_t)t * D_MODEL;

    float acc[NE];
#pragma unroll
    for (int e = 0; e < NE; e++) acc[e] = 0.f;
    for (int i = 0; i < D_MODEL / 32; i++) {
        int d = i * 32 + lane;
        float xv = xr[d];
#pragma unroll
        for (int e = 0; e < NE; e++) acc[e] += xv * gws[e * D_MODEL + d];
    }
#pragma unroll
    for (int e = 0; e < NE; e++)
        for (int off = 16; off > 0; off >>= 1)
            acc[e] += __shfl_xor_sync(0xffffffffu, acc[e], off);

    if (lane == 0) {
        float l[NE], p[NE];
        float m = -1e30f;
#pragma unroll
        for (int e = 0; e < NE; e++) { l[e] = acc[e] + gb[e]; m = fmaxf(m, l[e]); }
        float s = 0.f;
#pragma unroll
        for (int e = 0; e < NE; e++) { p[e] = expf(l[e] - m); s += p[e]; }
        float inv = 1.f / s;
#pragma unroll
        for (int e = 0; e < NE; e++) { p[e] *= inv; atomicAdd(&psum[e], p[e]); }
        int e1 = 0;
#pragma unroll
        for (int e = 1; e < NE; e++) if (p[e] > p[e1]) e1 = e;
        int e2 = -1;
#pragma unroll
        for (int e = 0; e < NE; e++) {
            if (e == e1) continue;
            if (e2 < 0 || p[e] > p[e2]) e2 = e;
        }
        float pr = 1.f / (p[e1] + p[e2]);
        g_topk_idx[2 * t] = e1;     g_topk_idx[2 * t + 1] = e2;
        g_topk_prob[2 * t] = p[e1] * pr; g_topk_prob[2 * t + 1] = p[e2] * pr;
        atomicAdd(&scnt[e1], 1);
        atomicAdd(&scnt[e2], 1);
    }
    __syncthreads();
    if (tid < NE) {
        atomicAdd(&g_probs_sum[tid], psum[tid]);
        atomicAdd(&g_counts[tid], scnt[tid]);
    }
}

// ---------------- stats + padded segment offsets ----------------
__global__ void k_stats(float* __restrict__ out) {
    if (threadIdx.x == 0) {
        int off = 0;
        for (int e = 0; e < NE; e++) {
            g_poff[e] = off;
            off += ((g_counts[e] + 127) >> 7) << 7;
        }
        g_poff[NE] = off;
        float* tail = out + (size_t)NT * D_MODEL;
        for (int e = 0; e < NE; e++) tail[e] = (float)g_counts[e] / (float)(NT * 2);
        float avg[NE], mean = 0.f;
        for (int e = 0; e < NE; e++) { avg[e] = g_probs_sum[e] / (float)NT; mean += avg[e]; }
        mean /= (float)NE;
        float var = 0.f;
        for (int e = 0; e < NE; e++) { float d = avg[e] - mean; var += d * d; }
        tail[NE] = var / (float)(NE - 1);   // ddof=1
    }
}

// ---------------- pack (fused scatter): claim slot, gather + fp16-convert row --
__global__ void __launch_bounds__(256) k_pack(const float* __restrict__ x) {
    __shared__ int s_p;
    int s = blockIdx.x;
    int tok = s >> 1;
    if (threadIdx.x == 0) {
        int e = g_topk_idx[s];
        int p = g_poff[e] + atomicAdd(&g_cursor[e], 1);
        g_pos[s] = p;
        s_p = p;
    }
    __syncthreads();
    int p = s_p;
    int i = threadIdx.x;
    float4 v = *(const float4*)&x[(size_t)tok * D_MODEL + i * 4];
    __half2* d = (__half2*)&g_xa[(size_t)p * D_MODEL + i * 4];
    d[0] = __floats2half2_rn(v.x, v.y);
    d[1] = __floats2half2_rn(v.z, v.w);
}

// ---------------- weight transpose to K-major fp16 -----------------
template <int R, int C>
__global__ void __launch_bounds__(256) k_transpose(const float* __restrict__ src,
                                                   __half* __restrict__ dst) {
    __shared__ float t[32][33];
    int e = blockIdx.z;
    const float* s = src + (size_t)e * R * C;
    __half* d = dst + (size_t)e * R * C;
    int c0 = blockIdx.x * 32, r0 = blockIdx.y * 32;
#pragma unroll
    for (int j = 0; j < 32; j += 8)
        t[threadIdx.y + j][threadIdx.x] =
            s[(size_t)(r0 + threadIdx.y + j) * C + c0 + threadIdx.x];
    __syncthreads();
#pragma unroll
    for (int j = 0; j < 32; j += 8)
        d[(size_t)(c0 + threadIdx.y + j) * R + r0 + threadIdx.x] =
            __float2half_rn(t[threadIdx.x][threadIdx.y + j]);
}

// ---------------- fp16 GEMM: 128x128 block, FOUR warps of 64x64, k64 chunks ----
// A stage: 128 rows x 72 halves (ldA=72 -> conflict-free scalar LDS), 18432B
// B stage: 128 n-rows x 72 halves (weights pre-transposed [e][n][k]),  18432B
// 64x64 warp tiles cut SMEM crossbar reads 1.5x vs 64x32 (the R13/14 binder)
#define A_STH 9216                         // halves per A stage
#define ST_BYTES (2 * A_STH * 2)           // 36864 bytes per stage
#define SMEM_GEMM (3 * ST_BYTES)           // 110592 -> 2 CTAs/SM

__device__ __forceinline__ void fill_stage(uint32_t aS, uint32_t bS,
                                           const __half* __restrict__ A0,
                                           const __half* __restrict__ B0,
                                           int koff, int kdim, int tid) {
#pragma unroll
    for (int i = 0; i < 8; i++) {          // A: 1024 cp16 (128 rows x 8 chunks)
        int id = tid + i * 128;
        int row = id >> 3, ch = id & 7;
        cp16(aS + (uint32_t)(row * 144 + ch * 16),
             A0 + (size_t)row * kdim + koff + ch * 8);
    }
#pragma unroll
    for (int i = 0; i < 8; i++) {          // B: 1024 cp16 (128 n-rows x 8 chunks)
        int id = tid + i * 128;
        int row = id >> 3, ch = id & 7;
        cp16(bS + (uint32_t)(row * 144 + ch * 16),
             B0 + (size_t)row * kdim + koff + ch * 8);
    }
}

template <int KDIM, int NDIM, bool FIRST>
__global__ void __launch_bounds__(128, 2) k_gemm(const __half* __restrict__ Bg,
                                                 const float* __restrict__ bias) {
    extern __shared__ char smc[];
    const int row0 = blockIdx.x * 128;
    if (row0 >= g_poff[NE]) return;
    int e = 0;
#pragma unroll
    for (int i = 1; i < NE; i++) if (row0 >= g_poff[i]) e = i;
    const int n0 = blockIdx.y * 128;
    const int tid = threadIdx.x, lane = tid & 31, warp = tid >> 5;
    const int wm = warp & 1, wn = warp >> 1;          // 2x2 grid of 64x64 warp tiles
    const int gid = lane >> 2, ktid = lane & 3;
    const uint32_t sb = smem_to_u32(smc);

    // resolve device symbols IN DEVICE CODE
    const __half* A0 = (FIRST ? g_xa : g_h) + (size_t)row0 * KDIM;
    const __half* B0 = Bg + (size_t)e * KDIM * NDIM + (size_t)n0 * KDIM;
    const int NKT = KDIM / 64;

    // prologue: 2 stages in flight
    fill_stage(sb, sb + A_STH * 2, A0, B0, 0, KDIM, tid);
    CP_COMMIT();
    fill_stage(sb + ST_BYTES, sb + ST_BYTES + A_STH * 2, A0, B0, 64, KDIM, tid);
    CP_COMMIT();

    float acc[4][8][4];
#pragma unroll
    for (int a = 0; a < 4; a++)
#pragma unroll
        for (int b = 0; b < 8; b++)
#pragma unroll
            for (int c = 0; c < 4; c++) acc[a][b][c] = 0.f;

    // per-thread fragment base offsets (words)
    const int aBase0 = (wm * 64 + gid) * 36 + ktid;   // + mt*16*36 + kkw(+4)
    const int bBase0 = (wn * 64 + gid) * 36 + ktid;   // + nt*8*36  + kkw(+4)

#pragma unroll 1
    for (int kt = 0; kt < NKT; kt++) {
        CP_WAIT(1);
        __syncthreads();
        const int cn = kt + 2;
        if (cn < NKT) {
            const uint32_t s2 = sb + (uint32_t)(cn % 3) * ST_BYTES;
            fill_stage(s2, s2 + A_STH * 2, A0, B0, cn * 64, KDIM, tid);
        }
        CP_COMMIT();
        const uint32_t* Aw = (const uint32_t*)(smc + (kt % 3) * ST_BYTES);
        const uint32_t* Bw = Aw + A_STH / 2;     // 4608 words

#pragma unroll
        for (int kk = 0; kk < 4; kk++) {         // 4 x k16
            const int kkw = kk * 8;
            unsigned a[4][4], b[8][2];
#pragma unroll
            for (int mt = 0; mt < 4; mt++) {
                int base = aBase0 + mt * (16 * 36) + kkw;
                a[mt][0] = Aw[base];
                a[mt][1] = Aw[base + 8 * 36];
                a[mt][2] = Aw[base + 4];
                a[mt][3] = Aw[base + 8 * 36 + 4];
            }
#pragma unroll
            for (int nt = 0; nt < 8; nt++) {
                int base = bBase0 + nt * (8 * 36) + kkw;
                b[nt][0] = Bw[base];
                b[nt][1] = Bw[base + 4];
            }
#pragma unroll
            for (int mt = 0; mt < 4; mt++)
#pragma unroll
                for (int nt = 0; nt < 8; nt++)
                    mma_f16(acc[mt][nt], a[mt], b[nt]);
        }
    }

    // epilogue
#pragma unroll
    for (int mt = 0; mt < 4; mt++) {
        int rr0 = row0 + wm * 64 + mt * 16 + gid;
        int rr1 = rr0 + 8;
#pragma unroll
        for (int nt = 0; nt < 8; nt++) {
            int c = n0 + wn * 64 + nt * 8 + ktid * 2;
            float* a = acc[mt][nt];
            if (FIRST) {
                float bb0 = bias[e * NDIM + c];
                float bb1 = bias[e * NDIM + c + 1];
                __half2 h0 = __floats2half2_rn(fmaxf(a[0] + bb0, 0.f),
                                               fmaxf(a[1] + bb1, 0.f));
                __half2 h1 = __floats2half2_rn(fmaxf(a[2] + bb0, 0.f),
                                               fmaxf(a[3] + bb1, 0.f));
                *(__half2*)&g_h[(size_t)rr0 * D_FF + c] = h0;
                *(__half2*)&g_h[(size_t)rr1 * D_FF + c] = h1;
            } else {
                *(float2*)&g_y[(size_t)rr0 * D_MODEL + c] = make_float2(a[0], a[1]);
                *(float2*)&g_y[(size_t)rr1 * D_MODEL + c] = make_float2(a[2], a[3]);
            }
        }
    }
}

// ---------------- combine ----------------
__global__ void __launch_bounds__(256) k_combine(const float* __restrict__ b2,
                                                 float* __restrict__ out) {
    int t = blockIdx.x, i = threadIdx.x;
    int e0 = g_topk_idx[2 * t], e1 = g_topk_idx[2 * t + 1];
    float p0 = g_topk_prob[2 * t], p1 = g_topk_prob[2 * t + 1];
    int q0 = g_pos[2 * t], q1 = g_pos[2 * t + 1];
    float4 y0 = *(const float4*)&g_y[(size_t)q0 * D_MODEL + i * 4];
    float4 y1 = *(const float4*)&g_y[(size_t)q1 * D_MODEL + i * 4];
    float4 c0 = *(const float4*)&b2[(size_t)e0 * D_MODEL + i * 4];
    float4 c1 = *(const float4*)&b2[(size_t)e1 * D_MODEL + i * 4];
    float4 o;
    o.x = p0 * (y0.x + c0.x) + p1 * (y1.x + c1.x);
    o.y = p0 * (y0.y + c0.y) + p1 * (y1.y + c1.y);
    o.z = p0 * (y0.z + c0.z) + p1 * (y1.z + c1.z);
    o.w = p0 * (y0.w + c0.w) + p1 * (y1.w + c1.w);
    *(float4*)&out[(size_t)t * D_MODEL + i * 4] = o;
}

// ---------------- launch ----------------
extern "C" void kernel_launch(void* const* d_in, const int* in_sizes, int n_in,
                              void* d_out, int out_size) {
    (void)in_sizes; (void)n_in; (void)out_size;
    const float* x  = (const float*)d_in[0];
    const float* gw = (const float*)d_in[1];
    const float* gb = (const float*)d_in[2];
    const float* w1 = (const float*)d_in[3];
    const float* b1 = (const float*)d_in[4];
    const float* w2 = (const float*)d_in[5];
    const float* b2 = (const float*)d_in[6];
    float* out = (float*)d_out;

    static int attr_done = 0;
    if (!attr_done) {
        cudaFuncSetAttribute(k_gemm<D_MODEL, D_FF, true>,
                             cudaFuncAttributeMaxDynamicSharedMemorySize, SMEM_GEMM);
        cudaFuncSetAttribute(k_gemm<D_FF, D_MODEL, false>,
                             cudaFuncAttributeMaxDynamicSharedMemorySize, SMEM_GEMM);
        attr_done = 1;
    }

    __half* w1h; cudaGetSymbolAddress((void**)&w1h, g_w1h);
    __half* w2h; cudaGetSymbolAddress((void**)&w2h, g_w2h);

    k_init<<<1, 32>>>();
    k_router<<<NT / 8, 256>>>(x, gw, gb);
    k_stats<<<1, 32>>>(out);
    k_pack<<<NT * 2, 256>>>(x);
    k_transpose<D_MODEL, D_FF><<<dim3(D_FF / 32, D_MODEL / 32, NE), dim3(32, 8)>>>(w1, w1h);
    k_transpose<D_FF, D_MODEL><<<dim3(D_MODEL / 32, D_FF / 32, NE), dim3(32, 8)>>>(w2, w2h);
    k_gemm<D_MODEL, D_FF, true ><<<dim3(NTILES, D_FF / 128), 128, SMEM_GEMM>>>(w1h, b1);
    k_gemm<D_FF, D_MODEL, false><<<dim3(NTILES, D_MODEL / 128), 128, SMEM_GEMM>>>(w2h, (const float*)0);
    k_combine<<<NT, 256>>>(b2, out);
}